// round 10
// baseline (speedup 1.0000x reference)
#include <cuda_runtime.h>
#include <cuda_bf16.h>
#include <cstdint>

#define N_NODES  200000
#define N_EDGES  200000
#define N_GRAPHS 128
#define IN_F     256
#define HID_F    128
#define OUT_F    128

// ---------------- scratch (static device globals; no allocation) -------------
__device__ float g_H1[(size_t)N_NODES * HID_F];   // x @ W1
__device__ float g_A1[(size_t)N_NODES * HID_F];   // conv1 output (x2)
__device__ float g_H2[(size_t)N_NODES * HID_F];   // relu(A1)@W2a + R[batch]
__device__ float g_O [(size_t)N_NODES * HID_F];   // conv2 pre-relu
__device__ float g_deg [N_NODES];
__device__ float g_dinv[N_NODES];
__device__ float g_R   [N_GRAPHS * HID_F];        // relu(x[root]) @ W2[128:384]
__device__ float g_gsum[N_GRAPHS * HID_F];
__device__ float g_gcnt[N_GRAPHS];
// transposed bf16 hi/lo weights: Wt[n*K + k]
__device__ __nv_bfloat16 g_Wt1h[HID_F * IN_F];
__device__ __nv_bfloat16 g_Wt1l[HID_F * IN_F];
__device__ __nv_bfloat16 g_Wt2h[HID_F * HID_F];
__device__ __nv_bfloat16 g_Wt2l[HID_F * HID_F];

// ---------------- helpers -----------------------------------------------------
__device__ __forceinline__ void mma_bf16(float* c, const uint32_t* a, const uint32_t* b) {
    asm volatile(
        "mma.sync.aligned.m16n8k16.row.col.f32.bf16.bf16.f32 "
        "{%0,%1,%2,%3}, {%4,%5,%6,%7}, {%8,%9}, {%0,%1,%2,%3};"
        : "+f"(c[0]), "+f"(c[1]), "+f"(c[2]), "+f"(c[3])
        : "r"(a[0]), "r"(a[1]), "r"(a[2]), "r"(a[3]), "r"(b[0]), "r"(b[1]));
}

__device__ __forceinline__ void ldmx4(uint32_t* r, uint32_t saddr) {
    asm volatile("ldmatrix.sync.aligned.m8n8.x4.shared.b16 {%0,%1,%2,%3}, [%4];"
        : "=r"(r[0]), "=r"(r[1]), "=r"(r[2]), "=r"(r[3]) : "r"(saddr));
}

__device__ __forceinline__ uint32_t smem_u32(const void* p) {
    uint32_t a;
    asm("{ .reg .u64 t; cvta.to.shared.u64 t, %1; cvt.u32.u64 %0, t; }"
        : "=r"(a) : "l"(p));
    return a;
}

__device__ __forceinline__ void split2(float a, float b, uint32_t& h, uint32_t& l) {
    __nv_bfloat162 hh = __floats2bfloat162_rn(a, b);
    float ra = a - __bfloat162float(hh.x);
    float rb = b - __bfloat162float(hh.y);
    __nv_bfloat162 ll = __floats2bfloat162_rn(ra, rb);
    h = *reinterpret_cast<uint32_t*>(&hh);
    l = *reinterpret_cast<uint32_t*>(&ll);
}

__device__ __forceinline__ void red_v4(float* addr, float a, float b, float c, float d) {
    asm volatile("red.global.add.v4.f32 [%0], {%1, %2, %3, %4};"
        :: "l"(addr), "f"(a), "f"(b), "f"(c), "f"(d) : "memory");
}

// ---------------- small kernels ----------------------------------------------
__global__ void k_init(void) {
    int i = blockIdx.x * blockDim.x + threadIdx.x;
    if (i < N_NODES) g_deg[i] = 1.0f;           // self-loop
    if (i < N_GRAPHS * HID_F) g_gsum[i] = 0.0f;
    if (i < N_GRAPHS) g_gcnt[i] = 0.0f;
}

__global__ void k_degree(const int* __restrict__ ei) {
    int e = blockIdx.x * blockDim.x + threadIdx.x;
    if (e >= N_EDGES) return;
    atomicAdd(&g_deg[ei[N_EDGES + e]], 1.0f);
}

__global__ void k_dinv(void) {
    int i = blockIdx.x * blockDim.x + threadIdx.x;
    if (i >= N_NODES) return;
    g_dinv[i] = rsqrtf(g_deg[i]);
}

// transpose + bf16 hi/lo split of weights: Wt[n*K+k] = split(W[k*HID+n])
__global__ void k_prepW(const float* __restrict__ W1, const float* __restrict__ W2) {
    int n = blockIdx.x;      // 0..127
    int k = threadIdx.x;     // 0..255
    float v = W1[(size_t)k * HID_F + n];
    __nv_bfloat16 h = __float2bfloat16(v);
    g_Wt1h[n * IN_F + k] = h;
    g_Wt1l[n * IN_F + k] = __float2bfloat16(v - __bfloat162float(h));
    if (k < HID_F) {
        float v2 = W2[(size_t)k * OUT_F + n];
        __nv_bfloat16 h2 = __float2bfloat16(v2);
        g_Wt2h[n * HID_F + k] = h2;
        g_Wt2l[n * HID_F + k] = __float2bfloat16(v2 - __bfloat162float(h2));
    }
}

// one warp per edge: D[dst] += H[src] * dinv[src]*dinv[dst]   (v4 reductions)
__global__ void k_edge(const float* __restrict__ H, float* __restrict__ D,
                       const int* __restrict__ ei) {
    int e = blockIdx.x * (blockDim.x >> 5) + (threadIdx.x >> 5);
    if (e >= N_EDGES) return;
    int lane = threadIdx.x & 31;
    int s = ei[e], d = ei[N_EDGES + e];
    float c = g_dinv[s] * g_dinv[d];
    float4 v = *(const float4*)(H + (size_t)s * HID_F + lane * 4);
    float* o = D + (size_t)d * HID_F + lane * 4;
    red_v4(o, v.x * c, v.y * c, v.z * c, v.w * c);
}

// R[g] = relu(x[root[g]]) @ W2[128:384]
__global__ void k_rootgemm(const float* __restrict__ x,
                           const int* __restrict__ root,
                           const float* __restrict__ W2) {
    __shared__ float xr[IN_F];
    int g = blockIdx.x, t = threadIdx.x;
    int r = root[g];
    xr[t]       = fmaxf(x[(size_t)r * IN_F + t], 0.0f);
    xr[t + 128] = fmaxf(x[(size_t)r * IN_F + t + 128], 0.0f);
    __syncthreads();
    float acc = 0.0f;
#pragma unroll 8
    for (int k = 0; k < IN_F; k++)
        acc += xr[k] * W2[(size_t)(HID_F + k) * OUT_F + t];
    g_R[g * HID_F + t] = acc;
}

// ---------------- tensor-core GEMM: C[M,128] = op(A[M,K]) @ Wt^T --------------
// mma.sync m16n8k16 bf16, 3-term split (hi*hi + hi*lo + lo*hi), fp32 accum.
// Fragment loads via ldmatrix.x4: 12 LDSM replace 96 LDS.32 per warp per chunk.
// Fused epilogue: H = C (+ R[batch]);  D = H * dinv^2 + bias.
#define BK   32
#define SAPD 40      // smem stride in halves (pad 8)

template<int K, bool RELU_A, bool ADD_R>
__global__ __launch_bounds__(256, 2)
void k_tgemm(const float* __restrict__ A,
             const __nv_bfloat16* __restrict__ Bh,
             const __nv_bfloat16* __restrict__ Bl,
             float* __restrict__ H, float* __restrict__ D,
             const float* __restrict__ bias,
             const int* __restrict__ batch, int M) {
    __shared__ uint16_t sA[2][128 * SAPD];  // [hi|lo][row*SAPD + k]
    __shared__ uint16_t sB[2][128 * SAPD];  // [hi|lo][n*SAPD + k]

    const int tid  = threadIdx.x;
    const int wid  = tid >> 5;
    const int lane = tid & 31;
    const int g8   = lane >> 2;            // 0..7
    const int t2   = (lane & 3) * 2;       // 0,2,4,6
    const int warp_m = (wid >> 2) * 64;    // 0 or 64
    const int warp_n = (wid & 3) * 32;     // 0..96
    const int blockRow = blockIdx.x * 128;

    const uint32_t sA0b = smem_u32(&sA[0][0]);
    const uint32_t sA1b = smem_u32(&sA[1][0]);
    const uint32_t sB0b = smem_u32(&sB[0][0]);
    const uint32_t sB1b = smem_u32(&sB[1][0]);

    // ldmatrix per-lane address pieces
    const int a_row_off = ((lane >> 3) & 1) * 8 + (lane & 7);  // within 16-row tile
    const int a_col_off = ((lane >> 4) & 1) * 8;               // k half
    const int b_n_off   = ((lane >> 4) & 1) * 8 + (lane & 7);  // within 16-n pair
    const int b_col_off = ((lane >> 3) & 1) * 8;               // k half

    float acc[4][4][4];
#pragma unroll
    for (int i = 0; i < 4; i++)
#pragma unroll
        for (int j = 0; j < 4; j++)
#pragma unroll
            for (int q = 0; q < 4; q++) acc[i][j][q] = 0.0f;

    for (int k0 = 0; k0 < K; k0 += BK) {
        __syncthreads();
        // ---- A tile: 128 x 32 fp32 -> split bf16 hi/lo ----
#pragma unroll
        for (int it = 0; it < 4; it++) {
            int linear = tid + it * 256;          // 0..1023 float4 slots
            int row = linear >> 3;
            int c4  = (linear & 7) * 4;
            int gr = blockRow + row;
            float4 v = make_float4(0.f, 0.f, 0.f, 0.f);
            if (gr < M) v = *(const float4*)(A + (size_t)gr * K + k0 + c4);
            if (RELU_A) {
                v.x = fmaxf(v.x, 0.f); v.y = fmaxf(v.y, 0.f);
                v.z = fmaxf(v.z, 0.f); v.w = fmaxf(v.w, 0.f);
            }
            uint32_t h01, l01, h23, l23;
            split2(v.x, v.y, h01, l01);
            split2(v.z, v.w, h23, l23);
            int ho = row * SAPD + c4;
            *(uint32_t*)&sA[0][ho]     = h01;
            *(uint32_t*)&sA[0][ho + 2] = h23;
            *(uint32_t*)&sA[1][ho]     = l01;
            *(uint32_t*)&sA[1][ho + 2] = l23;
        }
        // ---- B tiles: 128 n x 32 k bf16 (pretransposed, presplit) ----
#pragma unroll
        for (int it = 0; it < 2; it++) {
            int linear = tid + it * 256;          // 0..511 uint4 slots
            int n  = linear >> 2;
            int k8 = (linear & 3) * 8;
            size_t gi = ((size_t)n * K + k0 + k8) / 8;   // uint4 index
            int ho = n * SAPD + k8;
            *(uint4*)&sB[0][ho] = ((const uint4*)Bh)[gi];
            *(uint4*)&sB[1][ho] = ((const uint4*)Bl)[gi];
        }
        __syncthreads();

        // ---- compute: 2 k16-steps x 3 split terms x (4m x 4n) mma ----
#pragma unroll
        for (int ks = 0; ks < 2; ks++) {
            const int kk = ks * 16;
            uint32_t ah[4][4], al[4][4], bh[4][2], bl[4][2];
#pragma unroll
            for (int mt = 0; mt < 4; mt++) {
                int r = warp_m + mt * 16 + a_row_off;
                uint32_t off = (uint32_t)(r * SAPD + kk + a_col_off) * 2;
                ldmx4(ah[mt], sA0b + off);
                ldmx4(al[mt], sA1b + off);
            }
#pragma unroll
            for (int ntp = 0; ntp < 2; ntp++) {
                int n = warp_n + ntp * 16 + b_n_off;
                uint32_t off = (uint32_t)(n * SAPD + kk + b_col_off) * 2;
                uint32_t t[4];
                ldmx4(t, sB0b + off);
                bh[2 * ntp][0] = t[0]; bh[2 * ntp][1] = t[1];
                bh[2 * ntp + 1][0] = t[2]; bh[2 * ntp + 1][1] = t[3];
                ldmx4(t, sB1b + off);
                bl[2 * ntp][0] = t[0]; bl[2 * ntp][1] = t[1];
                bl[2 * ntp + 1][0] = t[2]; bl[2 * ntp + 1][1] = t[3];
            }
#pragma unroll
            for (int mt = 0; mt < 4; mt++)
#pragma unroll
                for (int nt = 0; nt < 4; nt++) {
                    mma_bf16(acc[mt][nt], ah[mt], bh[nt]);
                    mma_bf16(acc[mt][nt], ah[mt], bl[nt]);
                    mma_bf16(acc[mt][nt], al[mt], bh[nt]);
                }
        }
    }

    // ---- epilogue: H = acc (+R[batch]);  D = H*dinv^2 + bias ----
#pragma unroll
    for (int mt = 0; mt < 4; mt++) {
#pragma unroll
        for (int half = 0; half < 2; half++) {
            int row = blockRow + warp_m + mt * 16 + g8 + half * 8;
            if (row >= M) continue;
            float dv = g_dinv[row];
            float ds = dv * dv;
            const float* Rrow = ADD_R ? (g_R + (size_t)batch[row] * HID_F) : nullptr;
#pragma unroll
            for (int nt = 0; nt < 4; nt++) {
                int col = warp_n + nt * 8 + t2;
                float v0 = acc[mt][nt][half * 2 + 0];
                float v1 = acc[mt][nt][half * 2 + 1];
                if (ADD_R) { v0 += Rrow[col]; v1 += Rrow[col + 1]; }
                *(float2*)(H + (size_t)row * HID_F + col) = make_float2(v0, v1);
                float b0 = bias[col], b1 = bias[col + 1];
                *(float2*)(D + (size_t)row * HID_F + col) =
                    make_float2(v0 * ds + b0, v1 * ds + b1);
            }
        }
    }
}

// ---------------- graph mean reduction (batch is sorted) ----------------------
#define NPB 512
__global__ void k_reduce(const int* __restrict__ batch) {
    int c = threadIdx.x;                      // 0..127 (column)
    int start = blockIdx.x * NPB;
    if (start >= N_NODES) return;
    int end = min(start + NPB, N_NODES);
    int curg = batch[start];
    float acc = 0.0f; int cnt = 0;
    for (int i = start; i < end; i++) {
        int g = batch[i];
        if (g != curg) {
            atomicAdd(&g_gsum[curg * HID_F + c], acc);
            if (c == 0) atomicAdd(&g_gcnt[curg], (float)cnt);
            acc = 0.0f; cnt = 0; curg = g;
        }
        acc += fmaxf(g_O[(size_t)i * HID_F + c], 0.0f);
        cnt++;
    }
    atomicAdd(&g_gsum[curg * HID_F + c], acc);
    if (c == 0) atomicAdd(&g_gcnt[curg], (float)cnt);
}

__global__ void k_final(const int* __restrict__ root, float* __restrict__ out) {
    int g = blockIdx.x, c = threadIdx.x;      // 256 threads
    float cnt = g_gcnt[g];
    float v;
    if (c < HID_F) {
        v = g_gsum[g * HID_F + c] / fmaxf(cnt, 1.0f);
    } else {
        v = (cnt > 0.0f) ? g_A1[(size_t)root[g] * HID_F + (c - HID_F)] : 0.0f;
    }
    out[g * 256 + c] = v;
}

// ---------------- launch ------------------------------------------------------
extern "C" void kernel_launch(void* const* d_in, const int* in_sizes, int n_in,
                              void* d_out, int out_size) {
    const float* x     = (const float*)d_in[0];
    const int*   ei    = (const int*)  d_in[1];
    const int*   batch = (const int*)  d_in[2];
    const int*   root  = (const int*)  d_in[3];
    const float* W1    = (const float*)d_in[4];
    const float* b1    = (const float*)d_in[5];
    const float* W2    = (const float*)d_in[6];
    const float* b2    = (const float*)d_in[7];
    float* out = (float*)d_out;

    float *H1, *A1, *H2, *O;
    __nv_bfloat16 *Wt1h, *Wt1l, *Wt2h, *Wt2l;
    cudaGetSymbolAddress((void**)&H1, g_H1);
    cudaGetSymbolAddress((void**)&A1, g_A1);
    cudaGetSymbolAddress((void**)&H2, g_H2);
    cudaGetSymbolAddress((void**)&O,  g_O);
    cudaGetSymbolAddress((void**)&Wt1h, g_Wt1h);
    cudaGetSymbolAddress((void**)&Wt1l, g_Wt1l);
    cudaGetSymbolAddress((void**)&Wt2h, g_Wt2h);
    cudaGetSymbolAddress((void**)&Wt2l, g_Wt2l);

    const int gemm_blocks = (N_NODES + 127) / 128;             // 1563
    const int edge_blocks = (N_EDGES + 7) / 8;                 // 8 edges/block @256thr

    // degree + norm + weight prep
    k_init  <<<(N_NODES + 255) / 256, 256>>>();
    k_degree<<<(N_EDGES + 255) / 256, 256>>>(ei);
    k_dinv  <<<(N_NODES + 255) / 256, 256>>>();
    k_prepW <<<HID_F, IN_F>>>(W1, W2);

    // conv1: H1 = x@W1 (tensor); A1 = H1*dinv^2 + b1 (fused); edges accumulate
    k_tgemm<IN_F, false, false><<<gemm_blocks, 256>>>(
        x, Wt1h, Wt1l, H1, A1, b1, batch, N_NODES);
    k_edge<<<edge_blocks, 256>>>(H1, A1, ei);

    // root-feature GEMM (factored second half of W2)
    k_rootgemm<<<N_GRAPHS, 128>>>(x, root, W2);

    // conv2: H2 = relu(A1)@W2a + R[batch]; O = H2*dinv^2 + b2; edges accumulate
    k_tgemm<HID_F, true, true><<<gemm_blocks, 256>>>(
        A1, Wt2h, Wt2l, H2, O, b2, batch, N_NODES);
    k_edge<<<edge_blocks, 256>>>(H2, O, ei);

    // graph mean + output
    k_reduce<<<(N_NODES + NPB - 1) / NPB, 128>>>(batch);
    k_final <<<N_GRAPHS, 256>>>(root, out);
}

// round 11
// speedup vs baseline: 1.4335x; 1.4335x over previous
#include <cuda_runtime.h>
#include <cuda_bf16.h>
#include <cstdint>

#define N_NODES  200000
#define N_EDGES  200000
#define N_GRAPHS 128
#define IN_F     256
#define HID_F    128
#define OUT_F    128

// ---------------- scratch (static device globals; no allocation) -------------
__device__ float g_H1[(size_t)N_NODES * HID_F];   // x @ W1
__device__ float g_A1[(size_t)N_NODES * HID_F];   // conv1 output (x2)
__device__ float g_H2[(size_t)N_NODES * HID_F];   // relu(A1)@W2a + R[batch]
__device__ float g_O [(size_t)N_NODES * HID_F];   // conv2 pre-relu
__device__ float g_deg [N_NODES];
__device__ float g_dinv[N_NODES];
__device__ float g_R   [N_GRAPHS * HID_F];        // relu(x[root]) @ W2[128:384]
__device__ float g_gsum[N_GRAPHS * HID_F];
__device__ float g_gcnt[N_GRAPHS];
// transposed bf16 hi/lo weights: Wt[n*K + k]
__device__ __nv_bfloat16 g_Wt1h[HID_F * IN_F];
__device__ __nv_bfloat16 g_Wt1l[HID_F * IN_F];
__device__ __nv_bfloat16 g_Wt2h[HID_F * HID_F];
__device__ __nv_bfloat16 g_Wt2l[HID_F * HID_F];

// ---------------- helpers -----------------------------------------------------
__device__ __forceinline__ void mma_bf16(float* c, const uint32_t* a, const uint32_t* b) {
    asm volatile(
        "mma.sync.aligned.m16n8k16.row.col.f32.bf16.bf16.f32 "
        "{%0,%1,%2,%3}, {%4,%5,%6,%7}, {%8,%9}, {%0,%1,%2,%3};"
        : "+f"(c[0]), "+f"(c[1]), "+f"(c[2]), "+f"(c[3])
        : "r"(a[0]), "r"(a[1]), "r"(a[2]), "r"(a[3]), "r"(b[0]), "r"(b[1]));
}

__device__ __forceinline__ void split2(float a, float b, uint32_t& h, uint32_t& l) {
    __nv_bfloat162 hh = __floats2bfloat162_rn(a, b);
    float ra = a - __bfloat162float(hh.x);
    float rb = b - __bfloat162float(hh.y);
    __nv_bfloat162 ll = __floats2bfloat162_rn(ra, rb);
    h = *reinterpret_cast<uint32_t*>(&hh);
    l = *reinterpret_cast<uint32_t*>(&ll);
}

__device__ __forceinline__ void red_v4(float* addr, float a, float b, float c, float d) {
    asm volatile("red.global.add.v4.f32 [%0], {%1, %2, %3, %4};"
        :: "l"(addr), "f"(a), "f"(b), "f"(c), "f"(d) : "memory");
}

// ---------------- fused init + weight prep ------------------------------------
// blocks [0,128): transpose + bf16 hi/lo split of W1/W2 column n = blockIdx
// blocks [128,...): init deg/gsum/gcnt
__global__ void k_initprep(const float* __restrict__ W1, const float* __restrict__ W2) {
    if (blockIdx.x < HID_F) {
        int n = blockIdx.x;      // 0..127
        int k = threadIdx.x;     // 0..255
        float v = W1[(size_t)k * HID_F + n];
        __nv_bfloat16 h = __float2bfloat16(v);
        g_Wt1h[n * IN_F + k] = h;
        g_Wt1l[n * IN_F + k] = __float2bfloat16(v - __bfloat162float(h));
        if (k < HID_F) {
            float v2 = W2[(size_t)k * OUT_F + n];
            __nv_bfloat16 h2 = __float2bfloat16(v2);
            g_Wt2h[n * HID_F + k] = h2;
            g_Wt2l[n * HID_F + k] = __float2bfloat16(v2 - __bfloat162float(h2));
        }
    } else {
        int i = (blockIdx.x - HID_F) * blockDim.x + threadIdx.x;
        if (i < N_NODES) g_deg[i] = 1.0f;           // self-loop
        if (i < N_GRAPHS * HID_F) g_gsum[i] = 0.0f;
        if (i < N_GRAPHS) g_gcnt[i] = 0.0f;
    }
}

__global__ void k_degree(const int* __restrict__ ei) {
    int e = blockIdx.x * blockDim.x + threadIdx.x;
    if (e >= N_EDGES) return;
    atomicAdd(&g_deg[ei[N_EDGES + e]], 1.0f);
}

__global__ void k_dinv(void) {
    int i = blockIdx.x * blockDim.x + threadIdx.x;
    if (i >= N_NODES) return;
    g_dinv[i] = rsqrtf(g_deg[i]);
}

// one warp per edge: D[dst] += H[src] * dinv[src]*dinv[dst]   (v4 reductions)
__global__ void k_edge(const float* __restrict__ H, float* __restrict__ D,
                       const int* __restrict__ ei) {
    int e = blockIdx.x * (blockDim.x >> 5) + (threadIdx.x >> 5);
    if (e >= N_EDGES) return;
    int lane = threadIdx.x & 31;
    int s = ei[e], d = ei[N_EDGES + e];
    float c = g_dinv[s] * g_dinv[d];
    float4 v = *(const float4*)(H + (size_t)s * HID_F + lane * 4);
    float* o = D + (size_t)d * HID_F + lane * 4;
    red_v4(o, v.x * c, v.y * c, v.z * c, v.w * c);
}

// R[g] = relu(x[root[g]]) @ W2[128:384]
__global__ void k_rootgemm(const float* __restrict__ x,
                           const int* __restrict__ root,
                           const float* __restrict__ W2) {
    __shared__ float xr[IN_F];
    int g = blockIdx.x, t = threadIdx.x;
    int r = root[g];
    xr[t]       = fmaxf(x[(size_t)r * IN_F + t], 0.0f);
    xr[t + 128] = fmaxf(x[(size_t)r * IN_F + t + 128], 0.0f);
    __syncthreads();
    float acc = 0.0f;
#pragma unroll 8
    for (int k = 0; k < IN_F; k++)
        acc += xr[k] * W2[(size_t)(HID_F + k) * OUT_F + t];
    g_R[g * HID_F + t] = acc;
}

// ---------------- tensor-core GEMM: C[M,128] = op(A[M,K]) @ Wt^T --------------
// mma.sync m16n8k16 bf16, 3-term split (hi*hi + hi*lo + lo*hi), fp32 accum.
// Exact round-3 (437us) configuration: 256 thr, scalar LDS frags, 2 syncs/chunk.
// Fused epilogue: H = C (+ R[batch]);  D = H * dinv^2 + bias.
#define BK   32
#define SAPD 40      // smem stride in halves (pad 8)

template<int K, bool RELU_A, bool ADD_R>
__global__ __launch_bounds__(256, 2)
void k_tgemm(const float* __restrict__ A,
             const __nv_bfloat16* __restrict__ Bh,
             const __nv_bfloat16* __restrict__ Bl,
             float* __restrict__ H, float* __restrict__ D,
             const float* __restrict__ bias,
             const int* __restrict__ batch, int M) {
    __shared__ uint16_t sA[2][128 * SAPD];  // [hi|lo][row*SAPD + k]
    __shared__ uint16_t sB[2][128 * SAPD];  // [hi|lo][n*SAPD + k]

    const int tid  = threadIdx.x;
    const int wid  = tid >> 5;
    const int lane = tid & 31;
    const int g8   = lane >> 2;            // 0..7
    const int t2   = (lane & 3) * 2;       // 0,2,4,6
    const int warp_m = (wid >> 2) * 64;    // 0 or 64
    const int warp_n = (wid & 3) * 32;     // 0..96
    const int blockRow = blockIdx.x * 128;

    float acc[4][4][4];
#pragma unroll
    for (int i = 0; i < 4; i++)
#pragma unroll
        for (int j = 0; j < 4; j++)
#pragma unroll
            for (int q = 0; q < 4; q++) acc[i][j][q] = 0.0f;

    for (int k0 = 0; k0 < K; k0 += BK) {
        __syncthreads();
        // ---- A tile: 128 x 32 fp32 -> split bf16 hi/lo ----
#pragma unroll
        for (int it = 0; it < 4; it++) {
            int linear = tid + it * 256;          // 0..1023 float4 slots
            int row = linear >> 3;
            int c4  = (linear & 7) * 4;
            int gr = blockRow + row;
            float4 v = make_float4(0.f, 0.f, 0.f, 0.f);
            if (gr < M) v = *(const float4*)(A + (size_t)gr * K + k0 + c4);
            if (RELU_A) {
                v.x = fmaxf(v.x, 0.f); v.y = fmaxf(v.y, 0.f);
                v.z = fmaxf(v.z, 0.f); v.w = fmaxf(v.w, 0.f);
            }
            uint32_t h01, l01, h23, l23;
            split2(v.x, v.y, h01, l01);
            split2(v.z, v.w, h23, l23);
            int ho = row * SAPD + c4;
            *(uint32_t*)&sA[0][ho]     = h01;
            *(uint32_t*)&sA[0][ho + 2] = h23;
            *(uint32_t*)&sA[1][ho]     = l01;
            *(uint32_t*)&sA[1][ho + 2] = l23;
        }
        // ---- B tiles: 128 n x 32 k bf16 (pretransposed, presplit) ----
#pragma unroll
        for (int it = 0; it < 2; it++) {
            int linear = tid + it * 256;          // 0..511 uint4 slots
            int n  = linear >> 2;
            int k8 = (linear & 3) * 8;
            size_t gi = ((size_t)n * K + k0 + k8) / 8;   // uint4 index
            int ho = n * SAPD + k8;
            *(uint4*)&sB[0][ho] = ((const uint4*)Bh)[gi];
            *(uint4*)&sB[1][ho] = ((const uint4*)Bl)[gi];
        }
        __syncthreads();

        // ---- compute: 2 k16-steps x 3 split terms x (4m x 4n) mma ----
#pragma unroll
        for (int ks = 0; ks < 2; ks++) {
            const int kk = ks * 16;
            uint32_t ah[4][4], al[4][4], bh[4][2], bl[4][2];
#pragma unroll
            for (int mt = 0; mt < 4; mt++) {
                int r = warp_m + mt * 16 + g8;
                int ho = r * SAPD + kk + t2;
                ah[mt][0] = *(const uint32_t*)&sA[0][ho];
                ah[mt][1] = *(const uint32_t*)&sA[0][ho + 8 * SAPD];
                ah[mt][2] = *(const uint32_t*)&sA[0][ho + 8];
                ah[mt][3] = *(const uint32_t*)&sA[0][ho + 8 * SAPD + 8];
                al[mt][0] = *(const uint32_t*)&sA[1][ho];
                al[mt][1] = *(const uint32_t*)&sA[1][ho + 8 * SAPD];
                al[mt][2] = *(const uint32_t*)&sA[1][ho + 8];
                al[mt][3] = *(const uint32_t*)&sA[1][ho + 8 * SAPD + 8];
            }
#pragma unroll
            for (int nt = 0; nt < 4; nt++) {
                int n = warp_n + nt * 8 + g8;
                int ho = n * SAPD + kk + t2;
                bh[nt][0] = *(const uint32_t*)&sB[0][ho];
                bh[nt][1] = *(const uint32_t*)&sB[0][ho + 8];
                bl[nt][0] = *(const uint32_t*)&sB[1][ho];
                bl[nt][1] = *(const uint32_t*)&sB[1][ho + 8];
            }
#pragma unroll
            for (int mt = 0; mt < 4; mt++)
#pragma unroll
                for (int nt = 0; nt < 4; nt++) {
                    mma_bf16(acc[mt][nt], ah[mt], bh[nt]);
                    mma_bf16(acc[mt][nt], ah[mt], bl[nt]);
                    mma_bf16(acc[mt][nt], al[mt], bh[nt]);
                }
        }
    }

    // ---- epilogue: H = acc (+R[batch]);  D = H*dinv^2 + bias ----
#pragma unroll
    for (int mt = 0; mt < 4; mt++) {
#pragma unroll
        for (int half = 0; half < 2; half++) {
            int row = blockRow + warp_m + mt * 16 + g8 + half * 8;
            if (row >= M) continue;
            float dv = g_dinv[row];
            float ds = dv * dv;
            const float* Rrow = ADD_R ? (g_R + (size_t)batch[row] * HID_F) : nullptr;
#pragma unroll
            for (int nt = 0; nt < 4; nt++) {
                int col = warp_n + nt * 8 + t2;
                float v0 = acc[mt][nt][half * 2 + 0];
                float v1 = acc[mt][nt][half * 2 + 1];
                if (ADD_R) { v0 += Rrow[col]; v1 += Rrow[col + 1]; }
                *(float2*)(H + (size_t)row * HID_F + col) = make_float2(v0, v1);
                float b0 = bias[col], b1 = bias[col + 1];
                *(float2*)(D + (size_t)row * HID_F + col) =
                    make_float2(v0 * ds + b0, v1 * ds + b1);
            }
        }
    }
}

// ---------------- graph mean reduction (batch is sorted) ----------------------
#define NPB 128
__global__ void k_reduce(const int* __restrict__ batch) {
    int c = threadIdx.x;                      // 0..127 (column)
    int start = blockIdx.x * NPB;
    if (start >= N_NODES) return;
    int end = min(start + NPB, N_NODES);
    int curg = batch[start];
    float acc = 0.0f; int cnt = 0;
    for (int i = start; i < end; i++) {
        int g = batch[i];
        if (g != curg) {
            atomicAdd(&g_gsum[curg * HID_F + c], acc);
            if (c == 0) atomicAdd(&g_gcnt[curg], (float)cnt);
            acc = 0.0f; cnt = 0; curg = g;
        }
        acc += fmaxf(g_O[(size_t)i * HID_F + c], 0.0f);
        cnt++;
    }
    atomicAdd(&g_gsum[curg * HID_F + c], acc);
    if (c == 0) atomicAdd(&g_gcnt[curg], (float)cnt);
}

__global__ void k_final(const int* __restrict__ root, float* __restrict__ out) {
    int g = blockIdx.x, c = threadIdx.x;      // 256 threads
    float cnt = g_gcnt[g];
    float v;
    if (c < HID_F) {
        v = g_gsum[g * HID_F + c] / fmaxf(cnt, 1.0f);
    } else {
        v = (cnt > 0.0f) ? g_A1[(size_t)root[g] * HID_F + (c - HID_F)] : 0.0f;
    }
    out[g * 256 + c] = v;
}

// ---------------- launch ------------------------------------------------------
extern "C" void kernel_launch(void* const* d_in, const int* in_sizes, int n_in,
                              void* d_out, int out_size) {
    const float* x     = (const float*)d_in[0];
    const int*   ei    = (const int*)  d_in[1];
    const int*   batch = (const int*)  d_in[2];
    const int*   root  = (const int*)  d_in[3];
    const float* W1    = (const float*)d_in[4];
    const float* b1    = (const float*)d_in[5];
    const float* W2    = (const float*)d_in[6];
    const float* b2    = (const float*)d_in[7];
    float* out = (float*)d_out;

    float *H1, *A1, *H2, *O;
    __nv_bfloat16 *Wt1h, *Wt1l, *Wt2h, *Wt2l;
    cudaGetSymbolAddress((void**)&H1, g_H1);
    cudaGetSymbolAddress((void**)&A1, g_A1);
    cudaGetSymbolAddress((void**)&H2, g_H2);
    cudaGetSymbolAddress((void**)&O,  g_O);
    cudaGetSymbolAddress((void**)&Wt1h, g_Wt1h);
    cudaGetSymbolAddress((void**)&Wt1l, g_Wt1l);
    cudaGetSymbolAddress((void**)&Wt2h, g_Wt2h);
    cudaGetSymbolAddress((void**)&Wt2l, g_Wt2l);

    const int gemm_blocks = (N_NODES + 127) / 128;             // 1563
    const int edge_blocks = (N_EDGES + 7) / 8;                 // 8 edges/block @256thr
    const int init_blocks = HID_F + (N_NODES + 255) / 256;     // prep + init

    // init + weight prep (fused), degree, norm
    k_initprep<<<init_blocks, 256>>>(W1, W2);
    k_degree  <<<(N_EDGES + 255) / 256, 256>>>(ei);
    k_dinv    <<<(N_NODES + 255) / 256, 256>>>();

    // conv1: H1 = x@W1 (tensor); A1 = H1*dinv^2 + b1 (fused); edges accumulate
    k_tgemm<IN_F, false, false><<<gemm_blocks, 256>>>(
        x, Wt1h, Wt1l, H1, A1, b1, batch, N_NODES);
    k_edge<<<edge_blocks, 256>>>(H1, A1, ei);

    // root-feature GEMM (factored second half of W2)
    k_rootgemm<<<N_GRAPHS, 128>>>(x, root, W2);

    // conv2: H2 = relu(A1)@W2a + R[batch]; O = H2*dinv^2 + b2; edges accumulate
    k_tgemm<HID_F, true, true><<<gemm_blocks, 256>>>(
        A1, Wt2h, Wt2l, H2, O, b2, batch, N_NODES);
    k_edge<<<edge_blocks, 256>>>(H2, O, ei);

    // graph mean + output
    k_reduce<<<(N_NODES + NPB - 1) / NPB, 128>>>(batch);
    k_final <<<N_GRAPHS, 256>>>(root, out);
}

// round 12
// speedup vs baseline: 1.4552x; 1.0152x over previous
#include <cuda_runtime.h>
#include <cuda_bf16.h>
#include <cuda_fp16.h>
#include <cstdint>

#define N_NODES  200000
#define N_EDGES  200000
#define N_GRAPHS 128
#define IN_F     256
#define HID_F    128
#define OUT_F    128

// ---------------- scratch (static device globals; no allocation) -------------
__device__ __half g_H1[(size_t)N_NODES * HID_F];  // x @ W1            (fp16)
__device__ float  g_A1[(size_t)N_NODES * HID_F];  // conv1 output (x2)
__device__ __half g_H2[(size_t)N_NODES * HID_F];  // relu(A1)@W2a + R  (fp16)
__device__ float  g_O [(size_t)N_NODES * HID_F];  // conv2 pre-relu
__device__ float g_deg [N_NODES];
__device__ float g_dinv[N_NODES];
__device__ float g_R   [N_GRAPHS * HID_F];        // relu(x[root]) @ W2[128:384]
__device__ float g_gsum[N_GRAPHS * HID_F];
__device__ float g_gcnt[N_GRAPHS];
// transposed bf16 hi/lo weights: Wt[n*K + k]
__device__ __nv_bfloat16 g_Wt1h[HID_F * IN_F];
__device__ __nv_bfloat16 g_Wt1l[HID_F * IN_F];
__device__ __nv_bfloat16 g_Wt2h[HID_F * HID_F];
__device__ __nv_bfloat16 g_Wt2l[HID_F * HID_F];

// ---------------- helpers -----------------------------------------------------
__device__ __forceinline__ void mma_bf16(float* c, const uint32_t* a, const uint32_t* b) {
    asm volatile(
        "mma.sync.aligned.m16n8k16.row.col.f32.bf16.bf16.f32 "
        "{%0,%1,%2,%3}, {%4,%5,%6,%7}, {%8,%9}, {%0,%1,%2,%3};"
        : "+f"(c[0]), "+f"(c[1]), "+f"(c[2]), "+f"(c[3])
        : "r"(a[0]), "r"(a[1]), "r"(a[2]), "r"(a[3]), "r"(b[0]), "r"(b[1]));
}

__device__ __forceinline__ void split2(float a, float b, uint32_t& h, uint32_t& l) {
    __nv_bfloat162 hh = __floats2bfloat162_rn(a, b);
    float ra = a - __bfloat162float(hh.x);
    float rb = b - __bfloat162float(hh.y);
    __nv_bfloat162 ll = __floats2bfloat162_rn(ra, rb);
    h = *reinterpret_cast<uint32_t*>(&hh);
    l = *reinterpret_cast<uint32_t*>(&ll);
}

__device__ __forceinline__ void red_v4(float* addr, float a, float b, float c, float d) {
    asm volatile("red.global.add.v4.f32 [%0], {%1, %2, %3, %4};"
        :: "l"(addr), "f"(a), "f"(b), "f"(c), "f"(d) : "memory");
}

// ---------------- fused init + weight prep ------------------------------------
__global__ void k_initprep(const float* __restrict__ W1, const float* __restrict__ W2) {
    if (blockIdx.x < HID_F) {
        int n = blockIdx.x;      // 0..127
        int k = threadIdx.x;     // 0..255
        float v = W1[(size_t)k * HID_F + n];
        __nv_bfloat16 h = __float2bfloat16(v);
        g_Wt1h[n * IN_F + k] = h;
        g_Wt1l[n * IN_F + k] = __float2bfloat16(v - __bfloat162float(h));
        if (k < HID_F) {
            float v2 = W2[(size_t)k * OUT_F + n];
            __nv_bfloat16 h2 = __float2bfloat16(v2);
            g_Wt2h[n * HID_F + k] = h2;
            g_Wt2l[n * HID_F + k] = __float2bfloat16(v2 - __bfloat162float(h2));
        }
    } else {
        int i = (blockIdx.x - HID_F) * blockDim.x + threadIdx.x;
        if (i < N_NODES) g_deg[i] = 1.0f;           // self-loop
        if (i < N_GRAPHS * HID_F) g_gsum[i] = 0.0f;
        if (i < N_GRAPHS) g_gcnt[i] = 0.0f;
    }
}

__global__ void k_degree(const int* __restrict__ ei) {
    int e = blockIdx.x * blockDim.x + threadIdx.x;
    if (e >= N_EDGES) return;
    atomicAdd(&g_deg[ei[N_EDGES + e]], 1.0f);
}

__global__ void k_dinv(void) {
    int i = blockIdx.x * blockDim.x + threadIdx.x;
    if (i >= N_NODES) return;
    g_dinv[i] = rsqrtf(g_deg[i]);
}

// one warp per edge: D[dst] += H[src] * dinv[src]*dinv[dst]   (fp16 gather, v4 RED)
__global__ void k_edge(const __half* __restrict__ H, float* __restrict__ D,
                       const int* __restrict__ ei) {
    int e = blockIdx.x * (blockDim.x >> 5) + (threadIdx.x >> 5);
    if (e >= N_EDGES) return;
    int lane = threadIdx.x & 31;
    int s = ei[e], d = ei[N_EDGES + e];
    float c = g_dinv[s] * g_dinv[d];
    uint2 raw = *(const uint2*)(H + (size_t)s * HID_F + lane * 4);
    __half2 h0 = *reinterpret_cast<__half2*>(&raw.x);
    __half2 h1 = *reinterpret_cast<__half2*>(&raw.y);
    float2 f0 = __half22float2(h0);
    float2 f1 = __half22float2(h1);
    float* o = D + (size_t)d * HID_F + lane * 4;
    red_v4(o, f0.x * c, f0.y * c, f1.x * c, f1.y * c);
}

// R[g] = relu(x[root[g]]) @ W2[128:384]
__global__ void k_rootgemm(const float* __restrict__ x,
                           const int* __restrict__ root,
                           const float* __restrict__ W2) {
    __shared__ float xr[IN_F];
    int g = blockIdx.x, t = threadIdx.x;
    int r = root[g];
    xr[t]       = fmaxf(x[(size_t)r * IN_F + t], 0.0f);
    xr[t + 128] = fmaxf(x[(size_t)r * IN_F + t + 128], 0.0f);
    __syncthreads();
    float acc = 0.0f;
#pragma unroll 8
    for (int k = 0; k < IN_F; k++)
        acc += xr[k] * W2[(size_t)(HID_F + k) * OUT_F + t];
    g_R[g * HID_F + t] = acc;
}

// ---------------- tensor-core GEMM: C[M,128] = op(A[M,K]) @ Wt^T --------------
// mma.sync m16n8k16 bf16, 3-term split (hi*hi + hi*lo + lo*hi), fp32 accum.
// Fused epilogue: H(fp16) = C (+ R[batch]);  D(fp32) = C * dinv^2 + bias.
#define BK   32
#define SAPD 40      // smem stride in halves (pad 8)

template<int K, bool RELU_A, bool ADD_R>
__global__ __launch_bounds__(256, 2)
void k_tgemm(const float* __restrict__ A,
             const __nv_bfloat16* __restrict__ Bh,
             const __nv_bfloat16* __restrict__ Bl,
             __half* __restrict__ H, float* __restrict__ D,
             const float* __restrict__ bias,
             const int* __restrict__ batch, int M) {
    __shared__ uint16_t sA[2][128 * SAPD];  // [hi|lo][row*SAPD + k]
    __shared__ uint16_t sB[2][128 * SAPD];  // [hi|lo][n*SAPD + k]

    const int tid  = threadIdx.x;
    const int wid  = tid >> 5;
    const int lane = tid & 31;
    const int g8   = lane >> 2;            // 0..7
    const int t2   = (lane & 3) * 2;       // 0,2,4,6
    const int warp_m = (wid >> 2) * 64;    // 0 or 64
    const int warp_n = (wid & 3) * 32;     // 0..96
    const int blockRow = blockIdx.x * 128;

    float acc[4][4][4];
#pragma unroll
    for (int i = 0; i < 4; i++)
#pragma unroll
        for (int j = 0; j < 4; j++)
#pragma unroll
            for (int q = 0; q < 4; q++) acc[i][j][q] = 0.0f;

    for (int k0 = 0; k0 < K; k0 += BK) {
        __syncthreads();
        // ---- A tile: 128 x 32 fp32 -> split bf16 hi/lo ----
#pragma unroll
        for (int it = 0; it < 4; it++) {
            int linear = tid + it * 256;          // 0..1023 float4 slots
            int row = linear >> 3;
            int c4  = (linear & 7) * 4;
            int gr = blockRow + row;
            float4 v = make_float4(0.f, 0.f, 0.f, 0.f);
            if (gr < M) v = *(const float4*)(A + (size_t)gr * K + k0 + c4);
            if (RELU_A) {
                v.x = fmaxf(v.x, 0.f); v.y = fmaxf(v.y, 0.f);
                v.z = fmaxf(v.z, 0.f); v.w = fmaxf(v.w, 0.f);
            }
            uint32_t h01, l01, h23, l23;
            split2(v.x, v.y, h01, l01);
            split2(v.z, v.w, h23, l23);
            int ho = row * SAPD + c4;
            *(uint32_t*)&sA[0][ho]     = h01;
            *(uint32_t*)&sA[0][ho + 2] = h23;
            *(uint32_t*)&sA[1][ho]     = l01;
            *(uint32_t*)&sA[1][ho + 2] = l23;
        }
        // ---- B tiles: 128 n x 32 k bf16 (pretransposed, presplit) ----
#pragma unroll
        for (int it = 0; it < 2; it++) {
            int linear = tid + it * 256;          // 0..511 uint4 slots
            int n  = linear >> 2;
            int k8 = (linear & 3) * 8;
            size_t gi = ((size_t)n * K + k0 + k8) / 8;   // uint4 index
            int ho = n * SAPD + k8;
            *(uint4*)&sB[0][ho] = ((const uint4*)Bh)[gi];
            *(uint4*)&sB[1][ho] = ((const uint4*)Bl)[gi];
        }
        __syncthreads();

        // ---- compute: 2 k16-steps x 3 split terms x (4m x 4n) mma ----
#pragma unroll
        for (int ks = 0; ks < 2; ks++) {
            const int kk = ks * 16;
            uint32_t ah[4][4], al[4][4], bh[4][2], bl[4][2];
#pragma unroll
            for (int mt = 0; mt < 4; mt++) {
                int r = warp_m + mt * 16 + g8;
                int ho = r * SAPD + kk + t2;
                ah[mt][0] = *(const uint32_t*)&sA[0][ho];
                ah[mt][1] = *(const uint32_t*)&sA[0][ho + 8 * SAPD];
                ah[mt][2] = *(const uint32_t*)&sA[0][ho + 8];
                ah[mt][3] = *(const uint32_t*)&sA[0][ho + 8 * SAPD + 8];
                al[mt][0] = *(const uint32_t*)&sA[1][ho];
                al[mt][1] = *(const uint32_t*)&sA[1][ho + 8 * SAPD];
                al[mt][2] = *(const uint32_t*)&sA[1][ho + 8];
                al[mt][3] = *(const uint32_t*)&sA[1][ho + 8 * SAPD + 8];
            }
#pragma unroll
            for (int nt = 0; nt < 4; nt++) {
                int n = warp_n + nt * 8 + g8;
                int ho = n * SAPD + kk + t2;
                bh[nt][0] = *(const uint32_t*)&sB[0][ho];
                bh[nt][1] = *(const uint32_t*)&sB[0][ho + 8];
                bl[nt][0] = *(const uint32_t*)&sB[1][ho];
                bl[nt][1] = *(const uint32_t*)&sB[1][ho + 8];
            }
#pragma unroll
            for (int mt = 0; mt < 4; mt++)
#pragma unroll
                for (int nt = 0; nt < 4; nt++) {
                    mma_bf16(acc[mt][nt], ah[mt], bh[nt]);
                    mma_bf16(acc[mt][nt], ah[mt], bl[nt]);
                    mma_bf16(acc[mt][nt], al[mt], bh[nt]);
                }
        }
    }

    // ---- epilogue: H(fp16) = acc (+R[batch]);  D = H*dinv^2 + bias ----
#pragma unroll
    for (int mt = 0; mt < 4; mt++) {
#pragma unroll
        for (int half = 0; half < 2; half++) {
            int row = blockRow + warp_m + mt * 16 + g8 + half * 8;
            if (row >= M) continue;
            float dv = g_dinv[row];
            float ds = dv * dv;
            const float* Rrow = ADD_R ? (g_R + (size_t)batch[row] * HID_F) : nullptr;
#pragma unroll
            for (int nt = 0; nt < 4; nt++) {
                int col = warp_n + nt * 8 + t2;
                float v0 = acc[mt][nt][half * 2 + 0];
                float v1 = acc[mt][nt][half * 2 + 1];
                if (ADD_R) { v0 += Rrow[col]; v1 += Rrow[col + 1]; }
                *(__half2*)(H + (size_t)row * HID_F + col) = __floats2half2_rn(v0, v1);
                float b0 = bias[col], b1 = bias[col + 1];
                *(float2*)(D + (size_t)row * HID_F + col) =
                    make_float2(v0 * ds + b0, v1 * ds + b1);
            }
        }
    }
}

// ---------------- graph mean reduction (batch is sorted) ----------------------
#define NPB 128
__global__ void k_reduce(const int* __restrict__ batch) {
    int c = threadIdx.x;                      // 0..127 (column)
    int start = blockIdx.x * NPB;
    if (start >= N_NODES) return;
    int end = min(start + NPB, N_NODES);
    int curg = batch[start];
    float acc = 0.0f; int cnt = 0;
    for (int i = start; i < end; i++) {
        int g = batch[i];
        if (g != curg) {
            atomicAdd(&g_gsum[curg * HID_F + c], acc);
            if (c == 0) atomicAdd(&g_gcnt[curg], (float)cnt);
            acc = 0.0f; cnt = 0; curg = g;
        }
        acc += fmaxf(g_O[(size_t)i * HID_F + c], 0.0f);
        cnt++;
    }
    atomicAdd(&g_gsum[curg * HID_F + c], acc);
    if (c == 0) atomicAdd(&g_gcnt[curg], (float)cnt);
}

__global__ void k_final(const int* __restrict__ root, float* __restrict__ out) {
    int g = blockIdx.x, c = threadIdx.x;      // 256 threads
    float cnt = g_gcnt[g];
    float v;
    if (c < HID_F) {
        v = g_gsum[g * HID_F + c] / fmaxf(cnt, 1.0f);
    } else {
        v = (cnt > 0.0f) ? g_A1[(size_t)root[g] * HID_F + (c - HID_F)] : 0.0f;
    }
    out[g * 256 + c] = v;
}

// ---------------- launch ------------------------------------------------------
extern "C" void kernel_launch(void* const* d_in, const int* in_sizes, int n_in,
                              void* d_out, int out_size) {
    const float* x     = (const float*)d_in[0];
    const int*   ei    = (const int*)  d_in[1];
    const int*   batch = (const int*)  d_in[2];
    const int*   root  = (const int*)  d_in[3];
    const float* W1    = (const float*)d_in[4];
    const float* b1    = (const float*)d_in[5];
    const float* W2    = (const float*)d_in[6];
    const float* b2    = (const float*)d_in[7];
    float* out = (float*)d_out;

    float *A1, *O;
    __half *H1, *H2;
    __nv_bfloat16 *Wt1h, *Wt1l, *Wt2h, *Wt2l;
    cudaGetSymbolAddress((void**)&H1, g_H1);
    cudaGetSymbolAddress((void**)&A1, g_A1);
    cudaGetSymbolAddress((void**)&H2, g_H2);
    cudaGetSymbolAddress((void**)&O,  g_O);
    cudaGetSymbolAddress((void**)&Wt1h, g_Wt1h);
    cudaGetSymbolAddress((void**)&Wt1l, g_Wt1l);
    cudaGetSymbolAddress((void**)&Wt2h, g_Wt2h);
    cudaGetSymbolAddress((void**)&Wt2l, g_Wt2l);

    const int gemm_blocks = (N_NODES + 127) / 128;             // 1563
    const int edge_blocks = (N_EDGES + 7) / 8;                 // 8 edges/block @256thr
    const int init_blocks = HID_F + (N_NODES + 255) / 256;     // prep + init

    // init + weight prep (fused), degree, norm
    k_initprep<<<init_blocks, 256>>>(W1, W2);
    k_degree  <<<(N_EDGES + 255) / 256, 256>>>(ei);
    k_dinv    <<<(N_NODES + 255) / 256, 256>>>();

    // conv1: H1 = x@W1 (tensor, fp16); A1 = H1*dinv^2 + b1 (fused); edges accumulate
    k_tgemm<IN_F, false, false><<<gemm_blocks, 256>>>(
        x, Wt1h, Wt1l, H1, A1, b1, batch, N_NODES);
    k_edge<<<edge_blocks, 256>>>(H1, A1, ei);

    // root-feature GEMM (factored second half of W2)
    k_rootgemm<<<N_GRAPHS, 128>>>(x, root, W2);

    // conv2: H2 = relu(A1)@W2a + R[batch] (fp16); O = H2*dinv^2 + b2; edges accumulate
    k_tgemm<HID_F, true, true><<<gemm_blocks, 256>>>(
        A1, Wt2h, Wt2l, H2, O, b2, batch, N_NODES);
    k_edge<<<edge_blocks, 256>>>(H2, O, ei);

    // graph mean + output
    k_reduce<<<(N_NODES + NPB - 1) / NPB, 128>>>(batch);
    k_final <<<N_GRAPHS, 256>>>(root, out);
}

// round 13
// speedup vs baseline: 1.5790x; 1.0851x over previous
#include <cuda_runtime.h>
#include <cuda_bf16.h>
#include <cuda_fp16.h>
#include <cstdint>

#define N_NODES  200000
#define N_EDGES  200000
#define N_GRAPHS 128
#define IN_F     256
#define HID_F    128
#define OUT_F    128

// ---------------- scratch (static device globals; no allocation) -------------
__device__ __half g_H1[(size_t)N_NODES * HID_F];  // x @ W1            (fp16)
__device__ float  g_A1[(size_t)N_NODES * HID_F];  // conv1 output (x2)
__device__ __half g_H2[(size_t)N_NODES * HID_F];  // relu(A1)@W2a + R  (fp16)
__device__ float  g_O [(size_t)N_NODES * HID_F];  // conv2 pre-relu
__device__ float g_deg [N_NODES];
__device__ float g_dinv[N_NODES];
__device__ float g_R   [N_GRAPHS * HID_F];        // relu(x[root]) @ W2[128:384]
__device__ float g_gsum[N_GRAPHS * HID_F];
__device__ float g_gcnt[N_GRAPHS];
// transposed fp16 hi/lo weights: Wt[n*K + k]  (2-term split: B = Bh + Bl)
__device__ __half g_Wt1h[HID_F * IN_F];
__device__ __half g_Wt1l[HID_F * IN_F];
__device__ __half g_Wt2h[HID_F * HID_F];
__device__ __half g_Wt2l[HID_F * HID_F];

// ---------------- helpers -----------------------------------------------------
__device__ __forceinline__ void mma_f16(float* c, const uint32_t* a, const uint32_t* b) {
    asm volatile(
        "mma.sync.aligned.m16n8k16.row.col.f32.f16.f16.f32 "
        "{%0,%1,%2,%3}, {%4,%5,%6,%7}, {%8,%9}, {%0,%1,%2,%3};"
        : "+f"(c[0]), "+f"(c[1]), "+f"(c[2]), "+f"(c[3])
        : "r"(a[0]), "r"(a[1]), "r"(a[2]), "r"(a[3]), "r"(b[0]), "r"(b[1]));
}

__device__ __forceinline__ void red_v4(float* addr, float a, float b, float c, float d) {
    asm volatile("red.global.add.v4.f32 [%0], {%1, %2, %3, %4};"
        :: "l"(addr), "f"(a), "f"(b), "f"(c), "f"(d) : "memory");
}

// ---------------- fused init + weight prep ------------------------------------
__global__ void k_initprep(const float* __restrict__ W1, const float* __restrict__ W2) {
    if (blockIdx.x < HID_F) {
        int n = blockIdx.x;      // 0..127
        int k = threadIdx.x;     // 0..255
        float v = W1[(size_t)k * HID_F + n];
        __half h = __float2half_rn(v);
        g_Wt1h[n * IN_F + k] = h;
        g_Wt1l[n * IN_F + k] = __float2half_rn(v - __half2float(h));
        if (k < HID_F) {
            float v2 = W2[(size_t)k * OUT_F + n];
            __half h2 = __float2half_rn(v2);
            g_Wt2h[n * HID_F + k] = h2;
            g_Wt2l[n * HID_F + k] = __float2half_rn(v2 - __half2float(h2));
        }
    } else {
        int i = (blockIdx.x - HID_F) * blockDim.x + threadIdx.x;
        if (i < N_NODES) g_deg[i] = 1.0f;           // self-loop
        if (i < N_GRAPHS * HID_F) g_gsum[i] = 0.0f;
        if (i < N_GRAPHS) g_gcnt[i] = 0.0f;
    }
}

__global__ void k_degree(const int* __restrict__ ei) {
    int e = blockIdx.x * blockDim.x + threadIdx.x;
    if (e >= N_EDGES) return;
    atomicAdd(&g_deg[ei[N_EDGES + e]], 1.0f);
}

__global__ void k_dinv(void) {
    int i = blockIdx.x * blockDim.x + threadIdx.x;
    if (i >= N_NODES) return;
    g_dinv[i] = rsqrtf(g_deg[i]);
}

// one warp per edge: D[dst] += H[src] * dinv[src]*dinv[dst]   (fp16 gather, v4 RED)
__global__ void k_edge(const __half* __restrict__ H, float* __restrict__ D,
                       const int* __restrict__ ei) {
    int e = blockIdx.x * (blockDim.x >> 5) + (threadIdx.x >> 5);
    if (e >= N_EDGES) return;
    int lane = threadIdx.x & 31;
    int s = ei[e], d = ei[N_EDGES + e];
    float c = g_dinv[s] * g_dinv[d];
    uint2 raw = *(const uint2*)(H + (size_t)s * HID_F + lane * 4);
    __half2 h0 = *reinterpret_cast<__half2*>(&raw.x);
    __half2 h1 = *reinterpret_cast<__half2*>(&raw.y);
    float2 f0 = __half22float2(h0);
    float2 f1 = __half22float2(h1);
    float* o = D + (size_t)d * HID_F + lane * 4;
    red_v4(o, f0.x * c, f0.y * c, f1.x * c, f1.y * c);
}

// R[g] = relu(x[root[g]]) @ W2[128:384]
__global__ void k_rootgemm(const float* __restrict__ x,
                           const int* __restrict__ root,
                           const float* __restrict__ W2) {
    __shared__ float xr[IN_F];
    int g = blockIdx.x, t = threadIdx.x;
    int r = root[g];
    xr[t]       = fmaxf(x[(size_t)r * IN_F + t], 0.0f);
    xr[t + 128] = fmaxf(x[(size_t)r * IN_F + t + 128], 0.0f);
    __syncthreads();
    float acc = 0.0f;
#pragma unroll 8
    for (int k = 0; k < IN_F; k++)
        acc += xr[k] * W2[(size_t)(HID_F + k) * OUT_F + t];
    g_R[g * HID_F + t] = acc;
}

// ---------------- tensor-core GEMM: C[M,128] = op(A[M,K]) @ Wt^T --------------
// mma.sync m16n8k16 fp16, 2-term split (Ah*Bh + Ah*Bl), fp32 accum.
// A rounded once to fp16; weights presplit fp16 hi/lo. 32 MMAs/chunk (was 48).
// Fused epilogue: H(fp16) = C (+ R[batch]);  D(fp32) = C * dinv^2 + bias.
#define BK   32
#define SAPD 40      // smem stride in halves (pad 8)

template<int K, bool RELU_A, bool ADD_R>
__global__ __launch_bounds__(256, 2)
void k_tgemm(const float* __restrict__ A,
             const __half* __restrict__ Bh,
             const __half* __restrict__ Bl,
             __half* __restrict__ H, float* __restrict__ D,
             const float* __restrict__ bias,
             const int* __restrict__ batch, int M) {
    __shared__ uint16_t sA[128 * SAPD];     // fp16 A  [row*SAPD + k]
    __shared__ uint16_t sB[2][128 * SAPD];  // [hi|lo][n*SAPD + k]

    const int tid  = threadIdx.x;
    const int wid  = tid >> 5;
    const int lane = tid & 31;
    const int g8   = lane >> 2;            // 0..7
    const int t2   = (lane & 3) * 2;       // 0,2,4,6
    const int warp_m = (wid >> 2) * 64;    // 0 or 64
    const int warp_n = (wid & 3) * 32;     // 0..96
    const int blockRow = blockIdx.x * 128;

    float acc[4][4][4];
#pragma unroll
    for (int i = 0; i < 4; i++)
#pragma unroll
        for (int j = 0; j < 4; j++)
#pragma unroll
            for (int q = 0; q < 4; q++) acc[i][j][q] = 0.0f;

    for (int k0 = 0; k0 < K; k0 += BK) {
        __syncthreads();
        // ---- A tile: 128 x 32 fp32 -> fp16 ----
#pragma unroll
        for (int it = 0; it < 4; it++) {
            int linear = tid + it * 256;          // 0..1023 float4 slots
            int row = linear >> 3;
            int c4  = (linear & 7) * 4;
            int gr = blockRow + row;
            float4 v = make_float4(0.f, 0.f, 0.f, 0.f);
            if (gr < M) v = *(const float4*)(A + (size_t)gr * K + k0 + c4);
            if (RELU_A) {
                v.x = fmaxf(v.x, 0.f); v.y = fmaxf(v.y, 0.f);
                v.z = fmaxf(v.z, 0.f); v.w = fmaxf(v.w, 0.f);
            }
            __half2 p0 = __floats2half2_rn(v.x, v.y);
            __half2 p1 = __floats2half2_rn(v.z, v.w);
            int ho = row * SAPD + c4;
            *(uint32_t*)&sA[ho]     = *reinterpret_cast<uint32_t*>(&p0);
            *(uint32_t*)&sA[ho + 2] = *reinterpret_cast<uint32_t*>(&p1);
        }
        // ---- B tiles: 128 n x 32 k fp16 (pretransposed, presplit) ----
#pragma unroll
        for (int it = 0; it < 2; it++) {
            int linear = tid + it * 256;          // 0..511 uint4 slots
            int n  = linear >> 2;
            int k8 = (linear & 3) * 8;
            size_t gi = ((size_t)n * K + k0 + k8) / 8;   // uint4 index
            int ho = n * SAPD + k8;
            *(uint4*)&sB[0][ho] = ((const uint4*)Bh)[gi];
            *(uint4*)&sB[1][ho] = ((const uint4*)Bl)[gi];
        }
        __syncthreads();

        // ---- compute: 2 k16-steps x 2 split terms x (4m x 4n) mma ----
#pragma unroll
        for (int ks = 0; ks < 2; ks++) {
            const int kk = ks * 16;
            uint32_t ah[4][4], bh[4][2], bl[4][2];
#pragma unroll
            for (int mt = 0; mt < 4; mt++) {
                int r = warp_m + mt * 16 + g8;
                int ho = r * SAPD + kk + t2;
                ah[mt][0] = *(const uint32_t*)&sA[ho];
                ah[mt][1] = *(const uint32_t*)&sA[ho + 8 * SAPD];
                ah[mt][2] = *(const uint32_t*)&sA[ho + 8];
                ah[mt][3] = *(const uint32_t*)&sA[ho + 8 * SAPD + 8];
            }
#pragma unroll
            for (int nt = 0; nt < 4; nt++) {
                int n = warp_n + nt * 8 + g8;
                int ho = n * SAPD + kk + t2;
                bh[nt][0] = *(const uint32_t*)&sB[0][ho];
                bh[nt][1] = *(const uint32_t*)&sB[0][ho + 8];
                bl[nt][0] = *(const uint32_t*)&sB[1][ho];
                bl[nt][1] = *(const uint32_t*)&sB[1][ho + 8];
            }
#pragma unroll
            for (int mt = 0; mt < 4; mt++)
#pragma unroll
                for (int nt = 0; nt < 4; nt++) {
                    mma_f16(acc[mt][nt], ah[mt], bh[nt]);
                    mma_f16(acc[mt][nt], ah[mt], bl[nt]);
                }
        }
    }

    // ---- epilogue: H(fp16) = acc (+R[batch]);  D = H*dinv^2 + bias ----
#pragma unroll
    for (int mt = 0; mt < 4; mt++) {
#pragma unroll
        for (int half = 0; half < 2; half++) {
            int row = blockRow + warp_m + mt * 16 + g8 + half * 8;
            if (row >= M) continue;
            float dv = g_dinv[row];
            float ds = dv * dv;
            const float* Rrow = ADD_R ? (g_R + (size_t)batch[row] * HID_F) : nullptr;
#pragma unroll
            for (int nt = 0; nt < 4; nt++) {
                int col = warp_n + nt * 8 + t2;
                float v0 = acc[mt][nt][half * 2 + 0];
                float v1 = acc[mt][nt][half * 2 + 1];
                if (ADD_R) { v0 += Rrow[col]; v1 += Rrow[col + 1]; }
                *(__half2*)(H + (size_t)row * HID_F + col) = __floats2half2_rn(v0, v1);
                float b0 = bias[col], b1 = bias[col + 1];
                *(float2*)(D + (size_t)row * HID_F + col) =
                    make_float2(v0 * ds + b0, v1 * ds + b1);
            }
        }
    }
}

// ---------------- graph mean reduction (batch is sorted) ----------------------
#define NPB 128
__global__ void k_reduce(const int* __restrict__ batch) {
    int c = threadIdx.x;                      // 0..127 (column)
    int start = blockIdx.x * NPB;
    if (start >= N_NODES) return;
    int end = min(start + NPB, N_NODES);
    int curg = batch[start];
    float acc = 0.0f; int cnt = 0;
    for (int i = start; i < end; i++) {
        int g = batch[i];
        if (g != curg) {
            atomicAdd(&g_gsum[curg * HID_F + c], acc);
            if (c == 0) atomicAdd(&g_gcnt[curg], (float)cnt);
            acc = 0.0f; cnt = 0; curg = g;
        }
        acc += fmaxf(g_O[(size_t)i * HID_F + c], 0.0f);
        cnt++;
    }
    atomicAdd(&g_gsum[curg * HID_F + c], acc);
    if (c == 0) atomicAdd(&g_gcnt[curg], (float)cnt);
}

__global__ void k_final(const int* __restrict__ root, float* __restrict__ out) {
    int g = blockIdx.x, c = threadIdx.x;      // 256 threads
    float cnt = g_gcnt[g];
    float v;
    if (c < HID_F) {
        v = g_gsum[g * HID_F + c] / fmaxf(cnt, 1.0f);
    } else {
        v = (cnt > 0.0f) ? g_A1[(size_t)root[g] * HID_F + (c - HID_F)] : 0.0f;
    }
    out[g * 256 + c] = v;
}

// ---------------- launch ------------------------------------------------------
extern "C" void kernel_launch(void* const* d_in, const int* in_sizes, int n_in,
                              void* d_out, int out_size) {
    const float* x     = (const float*)d_in[0];
    const int*   ei    = (const int*)  d_in[1];
    const int*   batch = (const int*)  d_in[2];
    const int*   root  = (const int*)  d_in[3];
    const float* W1    = (const float*)d_in[4];
    const float* b1    = (const float*)d_in[5];
    const float* W2    = (const float*)d_in[6];
    const float* b2    = (const float*)d_in[7];
    float* out = (float*)d_out;

    float *A1, *O;
    __half *H1, *H2;
    __half *Wt1h, *Wt1l, *Wt2h, *Wt2l;
    cudaGetSymbolAddress((void**)&H1, g_H1);
    cudaGetSymbolAddress((void**)&A1, g_A1);
    cudaGetSymbolAddress((void**)&H2, g_H2);
    cudaGetSymbolAddress((void**)&O,  g_O);
    cudaGetSymbolAddress((void**)&Wt1h, g_Wt1h);
    cudaGetSymbolAddress((void**)&Wt1l, g_Wt1l);
    cudaGetSymbolAddress((void**)&Wt2h, g_Wt2h);
    cudaGetSymbolAddress((void**)&Wt2l, g_Wt2l);

    const int gemm_blocks = (N_NODES + 127) / 128;             // 1563
    const int edge_blocks = (N_EDGES + 7) / 8;                 // 8 edges/block @256thr
    const int init_blocks = HID_F + (N_NODES + 255) / 256;     // prep + init

    // init + weight prep (fused), degree, norm
    k_initprep<<<init_blocks, 256>>>(W1, W2);
    k_degree  <<<(N_EDGES + 255) / 256, 256>>>(ei);
    k_dinv    <<<(N_NODES + 255) / 256, 256>>>();

    // conv1: H1 = x@W1 (tensor, fp16); A1 = H1*dinv^2 + b1 (fused); edges accumulate
    k_tgemm<IN_F, false, false><<<gemm_blocks, 256>>>(
        x, Wt1h, Wt1l, H1, A1, b1, batch, N_NODES);
    k_edge<<<edge_blocks, 256>>>(H1, A1, ei);

    // root-feature GEMM (factored second half of W2)
    k_rootgemm<<<N_GRAPHS, 128>>>(x, root, W2);

    // conv2: H2 = relu(A1)@W2a + R[batch] (fp16); O = H2*dinv^2 + b2; edges accumulate
    k_tgemm<HID_F, true, true><<<gemm_blocks, 256>>>(
        A1, Wt2h, Wt2l, H2, O, b2, batch, N_NODES);
    k_edge<<<edge_blocks, 256>>>(H2, O, ei);

    // graph mean + output
    k_reduce<<<(N_NODES + NPB - 1) / NPB, 128>>>(batch);
    k_final <<<N_GRAPHS, 256>>>(root, out);
}